// round 5
// baseline (speedup 1.0000x reference)
#include <cuda_runtime.h>

// Fixed problem shapes
#define NS      51
#define NG      204
#define T_LEN   2048
#define B_TOT   8192
#define ROWS    64
#define SLICES  8
#define RPS     8                  // rows per thread
#define NPACK   4                  // f32x2 packs per thread
#define GSIZE   408                // active threads per k-group
#define GSTRIDE 416                // warp-aligned group stride
#define NTHREADS 832
#define HP      68                 // float pitch per k-row of h
#define HSZ     (NS * HP)
#define WQP     52                 // float4 pitch per k-row of weight quads
#define STG_PITCH 18               // ull per stage slot (144B, 16B-aligned, conflict-free)
#define K_SPLIT 26                 // gpA: k in [0,26), gpB: k in [26,51)

typedef unsigned long long ull;

__device__ __forceinline__ ull pack2(float lo, float hi) {
    ull r; asm("mov.b64 %0, {%1, %2};" : "=l"(r) : "f"(lo), "f"(hi)); return r;
}
__device__ __forceinline__ ull fma2(ull a, ull b, ull c) {
    ull d; asm("fma.rn.f32x2 %0, %1, %2, %3;" : "=l"(d) : "l"(a), "l"(b), "l"(c)); return d;
}
__device__ __forceinline__ ull add2(ull a, ull b) {
    ull d; asm("add.rn.f32x2 %0, %1, %2;" : "=l"(d) : "l"(a), "l"(b)); return d;
}
__device__ __forceinline__ float2 unpack2(ull v) {
    float lo, hi; asm("mov.b64 {%0, %1}, %2;" : "=f"(lo), "=f"(hi) : "l"(v));
    return make_float2(lo, hi);
}
__device__ __forceinline__ float sigm(float v) {
    return 1.0f / (1.0f + __expf(-v));
}
__device__ __forceinline__ float tanh_fast(float v) {
    return 2.0f / (1.0f + __expf(-2.0f * v)) - 1.0f;
}

__device__ __forceinline__ void lstm_act2(ull Ai, ull Af, ull Ag, ull Ao,
                                          float* c, float* hn) {
    float2 ai = unpack2(Ai), af = unpack2(Af), ag = unpack2(Ag), ao = unpack2(Ao);
    float cx = fmaf(sigm(af.x), c[0], sigm(ai.x) * tanh_fast(ag.x));
    c[0] = cx;  hn[0] = sigm(ao.x) * tanh_fast(cx);
    float cy = fmaf(sigm(af.y), c[1], sigm(ai.y) * tanh_fast(ag.y));
    c[1] = cy;  hn[1] = sigm(ao.y) * tanh_fast(cy);
}

__global__ __launch_bounds__(NTHREADS, 1)
void lstm2_ksplit_kernel(
    const float* __restrict__ x,      // [B, T]
    const float* __restrict__ Wih1,   // [204, 1]
    const float* __restrict__ Whh1,   // [204, 51]
    const float* __restrict__ bih1,
    const float* __restrict__ bhh1,
    const float* __restrict__ Wih2,   // [204, 51]
    const float* __restrict__ Whh2,   // [204, 51]
    const float* __restrict__ bih2,
    const float* __restrict__ bhh2,
    const float* __restrict__ Wlin,   // [1, 51]
    const float* __restrict__ blin,
    float* __restrict__ out)          // [B, T]
{
    extern __shared__ float sm[];
    float4* wq1  = (float4*)sm;                       // [NS][WQP] gate quads of Whh1
    float4* wqi2 = wq1  + NS * WQP;
    float4* wqh2 = wqi2 + NS * WQP;
    ull*    stg  = (ull*)(wqh2 + NS * WQP);           // [408][STG_PITCH] partial stage
    float*  h1   = (float*)(stg + GSIZE * STG_PITCH); // [NS][HP]  (single buffer)
    float*  h2   = h1 + HSZ;
    float*  b1s  = h2 + HSZ;                          // [NG]
    float*  b2s  = b1s + NG;
    float*  wi1s = b2s + NG;                          // [NG]
    float*  wls  = wi1s + NG;                         // [52]
    float*  xs   = wls + 52;                          // [2][64]

    const int tid = threadIdx.x;
    const int rb  = blockIdx.x * ROWS;

    // ---- init ----
    for (int i = tid; i < NG * NS; i += NTHREADS) {
        int g = i / NS, k = i % NS;
        int jj = g % NS, gi = g / NS;
        ((float*)&wq1 [k * WQP + jj])[gi] = Whh1[i];
        ((float*)&wqi2[k * WQP + jj])[gi] = Wih2[i];
        ((float*)&wqh2[k * WQP + jj])[gi] = Whh2[i];
    }
    for (int i = tid; i < NG; i += NTHREADS) {
        b1s[i]  = bih1[i] + bhh1[i];
        b2s[i]  = bih2[i] + bhh2[i];
        wi1s[i] = Wih1[i];
    }
    for (int i = tid; i < NS; i += NTHREADS) wls[i] = Wlin[i];
    for (int i = tid; i < HSZ; i += NTHREADS) { h1[i] = 0.0f; h2[i] = 0.0f; }
    if (tid < ROWS) xs[tid] = x[(size_t)(rb + tid) * T_LEN];
    const float blin_v = blin[0];
    __syncthreads();

    const int  gp     = (tid >= GSTRIDE);      // 0: k-low (+x,+b1), 1: k-high
    const int  r      = tid - (gp ? GSTRIDE : 0);
    const bool active = (r < GSIZE);
    const int  j      = r % NS;                // hidden unit
    const int  sl     = (r / NS) & 7;          // row slice
    const int  r0     = sl * RPS;
    const int  slot   = sl * NS + j;
    ull* myStg = stg + (size_t)slot * STG_PITCH;

    const int kbeg = gp ? K_SPLIT : 0;
    const int kcnt = gp ? (NS - K_SPLIT) : K_SPLIT;   // 25 / 26

    // packed per-thread constants
    ull wxd[4], b1d[4], b2d[4];
    #pragma unroll
    for (int gi = 0; gi < 4; ++gi) {
        float wv  = wi1s[j + gi * NS];
        float bv1 = b1s[j + gi * NS];
        float bv2 = b2s[j + gi * NS];
        wxd[gi] = pack2(wv, wv);
        b1d[gi] = pack2(bv1, bv1);
        b2d[gi] = pack2(bv2, bv2);
    }

    float c1[RPS], c2[RPS];   // c1 used by gpA threads, c2 by gpB threads
    #pragma unroll
    for (int i = 0; i < RPS; ++i) { c1[i] = 0.0f; c2[i] = 0.0f; }

    for (int t = 0; t < T_LEN; ++t) {
        const float* xcur = xs + (t & 1) * 64;
        ull a0[NPACK], a1[NPACK], a2[NPACK], a3[NPACK];

        // ===== P1: layer-1 partial gates over own k-range =====
        if (active) {
            if (gp == 0) {
                ulonglong2 xA = *(const ulonglong2*)(xcur + r0);
                ulonglong2 xB = *(const ulonglong2*)(xcur + r0 + 4);
                ull xp[NPACK] = {xA.x, xA.y, xB.x, xB.y};
                #pragma unroll
                for (int p = 0; p < NPACK; ++p) {
                    a0[p] = fma2(xp[p], wxd[0], b1d[0]);
                    a1[p] = fma2(xp[p], wxd[1], b1d[1]);
                    a2[p] = fma2(xp[p], wxd[2], b1d[2]);
                    a3[p] = fma2(xp[p], wxd[3], b1d[3]);
                }
            } else {
                #pragma unroll
                for (int p = 0; p < NPACK; ++p) { a0[p]=0; a1[p]=0; a2[p]=0; a3[p]=0; }
            }
            const float4* wp = wq1 + kbeg * WQP + j;
            const float*  hp = h1 + kbeg * HP + r0;
            #pragma unroll 2
            for (int kk = 0; kk < kcnt; ++kk) {
                float4 w = *wp;  wp += WQP;
                ull w0 = pack2(w.x, w.x), w1 = pack2(w.y, w.y);
                ull w2 = pack2(w.z, w.z), w3 = pack2(w.w, w.w);
                ulonglong2 hA = *(const ulonglong2*)hp;
                ulonglong2 hB = *(const ulonglong2*)(hp + 4);
                hp += HP;
                ull hv[NPACK] = {hA.x, hA.y, hB.x, hB.y};
                #pragma unroll
                for (int p = 0; p < NPACK; ++p) {
                    a0[p] = fma2(hv[p], w0, a0[p]);
                    a1[p] = fma2(hv[p], w1, a1[p]);
                    a2[p] = fma2(hv[p], w2, a2[p]);
                    a3[p] = fma2(hv[p], w3, a3[p]);
                }
            }
            if (gp == 1) {   // publish partials
                *(ulonglong2*)(myStg +  0) = make_ulonglong2(a0[0], a0[1]);
                *(ulonglong2*)(myStg +  2) = make_ulonglong2(a0[2], a0[3]);
                *(ulonglong2*)(myStg +  4) = make_ulonglong2(a1[0], a1[1]);
                *(ulonglong2*)(myStg +  6) = make_ulonglong2(a1[2], a1[3]);
                *(ulonglong2*)(myStg +  8) = make_ulonglong2(a2[0], a2[1]);
                *(ulonglong2*)(myStg + 10) = make_ulonglong2(a2[2], a2[3]);
                *(ulonglong2*)(myStg + 12) = make_ulonglong2(a3[0], a3[1]);
                *(ulonglong2*)(myStg + 14) = make_ulonglong2(a3[2], a3[3]);
            }
        }
        __syncthreads();   // b1: partials ready; all h1 reads done

        // ===== P2: gpA reduce+act layer-1, write h1 in place;
        //           gpB: rows 0..63 project h2(t-1); 64..127 prefetch x(t+1) =====
        if (active && gp == 0) {
            ulonglong2 s0 = *(const ulonglong2*)(myStg +  0);
            ulonglong2 s1 = *(const ulonglong2*)(myStg +  2);
            ulonglong2 s2 = *(const ulonglong2*)(myStg +  4);
            ulonglong2 s3 = *(const ulonglong2*)(myStg +  6);
            ulonglong2 s4 = *(const ulonglong2*)(myStg +  8);
            ulonglong2 s5 = *(const ulonglong2*)(myStg + 10);
            ulonglong2 s6 = *(const ulonglong2*)(myStg + 12);
            ulonglong2 s7 = *(const ulonglong2*)(myStg + 14);
            a0[0]=add2(a0[0],s0.x); a0[1]=add2(a0[1],s0.y);
            a0[2]=add2(a0[2],s1.x); a0[3]=add2(a0[3],s1.y);
            a1[0]=add2(a1[0],s2.x); a1[1]=add2(a1[1],s2.y);
            a1[2]=add2(a1[2],s3.x); a1[3]=add2(a1[3],s3.y);
            a2[0]=add2(a2[0],s4.x); a2[1]=add2(a2[1],s4.y);
            a2[2]=add2(a2[2],s5.x); a2[3]=add2(a2[3],s5.y);
            a3[0]=add2(a3[0],s6.x); a3[1]=add2(a3[1],s6.y);
            a3[2]=add2(a3[2],s7.x); a3[3]=add2(a3[3],s7.y);
            float hn[RPS];
            #pragma unroll
            for (int p = 0; p < NPACK; ++p)
                lstm_act2(a0[p], a1[p], a2[p], a3[p], c1 + 2 * p, hn + 2 * p);
            float* dst = h1 + j * HP + r0;
            *(float4*)dst       = make_float4(hn[0], hn[1], hn[2], hn[3]);
            *(float4*)(dst + 4) = make_float4(hn[4], hn[5], hn[6], hn[7]);
        } else if (active && gp == 1) {
            if (r < ROWS) {
                if (t > 0) {   // h2 still holds step t-1 values
                    float acc = blin_v;
                    #pragma unroll 4
                    for (int k = 0; k < NS; ++k)
                        acc = fmaf(h2[k * HP + r], wls[k], acc);
                    out[(size_t)(rb + r) * T_LEN + (t - 1)] = acc;
                }
            } else if (r < 2 * ROWS) {
                int rr = r - ROWS;
                if (t + 1 < T_LEN)
                    xs[((t + 1) & 1) * 64 + rr] =
                        x[(size_t)(rb + rr) * T_LEN + (t + 1)];
            }
        }
        __syncthreads();   // b2: h1(new) visible

        // ===== P3: layer-2 partial gates over own k-range (h1 new, h2 old) =====
        if (active) {
            if (gp == 1) {
                #pragma unroll
                for (int p = 0; p < NPACK; ++p) {
                    a0[p] = b2d[0]; a1[p] = b2d[1]; a2[p] = b2d[2]; a3[p] = b2d[3];
                }
            } else {
                #pragma unroll
                for (int p = 0; p < NPACK; ++p) { a0[p]=0; a1[p]=0; a2[p]=0; a3[p]=0; }
            }
            const float4* wpi = wqi2 + kbeg * WQP + j;
            const float4* wph = wqh2 + kbeg * WQP + j;
            const float*  p1  = h1 + kbeg * HP + r0;
            const float*  p2  = h2 + kbeg * HP + r0;
            #pragma unroll 1
            for (int kk = 0; kk < kcnt; ++kk) {
                float4 wi = *wpi;  wpi += WQP;
                float4 wh = *wph;  wph += WQP;
                ulonglong2 h1A = *(const ulonglong2*)p1;
                ulonglong2 h1B = *(const ulonglong2*)(p1 + 4);
                p1 += HP;
                ulonglong2 h2A = *(const ulonglong2*)p2;
                ulonglong2 h2B = *(const ulonglong2*)(p2 + 4);
                p2 += HP;
                ull wi0 = pack2(wi.x, wi.x), wi1d = pack2(wi.y, wi.y);
                ull wi2d = pack2(wi.z, wi.z), wi3 = pack2(wi.w, wi.w);
                ull wh0 = pack2(wh.x, wh.x), wh1d = pack2(wh.y, wh.y);
                ull wh2d = pack2(wh.z, wh.z), wh3 = pack2(wh.w, wh.w);
                ull hv1[NPACK] = {h1A.x, h1A.y, h1B.x, h1B.y};
                ull hv2[NPACK] = {h2A.x, h2A.y, h2B.x, h2B.y};
                #pragma unroll
                for (int p = 0; p < NPACK; ++p) {
                    a0[p] = fma2(hv1[p], wi0,  a0[p]);
                    a1[p] = fma2(hv1[p], wi1d, a1[p]);
                    a2[p] = fma2(hv1[p], wi2d, a2[p]);
                    a3[p] = fma2(hv1[p], wi3,  a3[p]);
                    a0[p] = fma2(hv2[p], wh0,  a0[p]);
                    a1[p] = fma2(hv2[p], wh1d, a1[p]);
                    a2[p] = fma2(hv2[p], wh2d, a2[p]);
                    a3[p] = fma2(hv2[p], wh3,  a3[p]);
                }
            }
            if (gp == 0) {   // publish partials
                *(ulonglong2*)(myStg +  0) = make_ulonglong2(a0[0], a0[1]);
                *(ulonglong2*)(myStg +  2) = make_ulonglong2(a0[2], a0[3]);
                *(ulonglong2*)(myStg +  4) = make_ulonglong2(a1[0], a1[1]);
                *(ulonglong2*)(myStg +  6) = make_ulonglong2(a1[2], a1[3]);
                *(ulonglong2*)(myStg +  8) = make_ulonglong2(a2[0], a2[1]);
                *(ulonglong2*)(myStg + 10) = make_ulonglong2(a2[2], a2[3]);
                *(ulonglong2*)(myStg + 12) = make_ulonglong2(a3[0], a3[1]);
                *(ulonglong2*)(myStg + 14) = make_ulonglong2(a3[2], a3[3]);
            }
        }
        __syncthreads();   // b3: partials ready; all h2 reads done

        // ===== P4: gpB reduce+act layer-2, write h2 in place =====
        if (active && gp == 1) {
            ulonglong2 s0 = *(const ulonglong2*)(myStg +  0);
            ulonglong2 s1 = *(const ulonglong2*)(myStg +  2);
            ulonglong2 s2 = *(const ulonglong2*)(myStg +  4);
            ulonglong2 s3 = *(const ulonglong2*)(myStg +  6);
            ulonglong2 s4 = *(const ulonglong2*)(myStg +  8);
            ulonglong2 s5 = *(const ulonglong2*)(myStg + 10);
            ulonglong2 s6 = *(const ulonglong2*)(myStg + 12);
            ulonglong2 s7 = *(const ulonglong2*)(myStg + 14);
            a0[0]=add2(a0[0],s0.x); a0[1]=add2(a0[1],s0.y);
            a0[2]=add2(a0[2],s1.x); a0[3]=add2(a0[3],s1.y);
            a1[0]=add2(a1[0],s2.x); a1[1]=add2(a1[1],s2.y);
            a1[2]=add2(a1[2],s3.x); a1[3]=add2(a1[3],s3.y);
            a2[0]=add2(a2[0],s4.x); a2[1]=add2(a2[1],s4.y);
            a2[2]=add2(a2[2],s5.x); a2[3]=add2(a2[3],s5.y);
            a3[0]=add2(a3[0],s6.x); a3[1]=add2(a3[1],s6.y);
            a3[2]=add2(a3[2],s7.x); a3[3]=add2(a3[3],s7.y);
            float hn[RPS];
            #pragma unroll
            for (int p = 0; p < NPACK; ++p)
                lstm_act2(a0[p], a1[p], a2[p], a3[p], c2 + 2 * p, hn + 2 * p);
            float* dst = h2 + j * HP + r0;
            *(float4*)dst       = make_float4(hn[0], hn[1], hn[2], hn[3]);
            *(float4*)(dst + 4) = make_float4(hn[4], hn[5], hn[6], hn[7]);
        }
        __syncthreads();   // b4: h2(new) visible
    }

    // ---- final projection for t = T_LEN-1 ----
    if (active && gp == 1 && r < ROWS) {
        float acc = blin_v;
        #pragma unroll 4
        for (int k = 0; k < NS; ++k)
            acc = fmaf(h2[k * HP + r], wls[k], acc);
        out[(size_t)(rb + r) * T_LEN + (T_LEN - 1)] = acc;
    }
}

extern "C" void kernel_launch(void* const* d_in, const int* in_sizes, int n_in,
                              void* d_out, int out_size) {
    const float* x    = (const float*)d_in[0];
    const float* Wih1 = (const float*)d_in[1];
    const float* Whh1 = (const float*)d_in[2];
    const float* bih1 = (const float*)d_in[3];
    const float* bhh1 = (const float*)d_in[4];
    const float* Wih2 = (const float*)d_in[5];
    const float* Whh2 = (const float*)d_in[6];
    const float* bih2 = (const float*)d_in[7];
    const float* bhh2 = (const float*)d_in[8];
    const float* Wlin = (const float*)d_in[9];
    const float* blin = (const float*)d_in[10];
    float* out = (float*)d_out;

    size_t smem = (size_t)(3 * NS * WQP * 4) * sizeof(float)        // weight quads
                + (size_t)(GSIZE * STG_PITCH) * sizeof(ull)         // stage
                + (size_t)(2 * HSZ) * sizeof(float)                 // h1, h2
                + (size_t)(3 * NG + 52 + 128) * sizeof(float);      // biases, wlin, xs
    cudaFuncSetAttribute(lstm2_ksplit_kernel,
                         cudaFuncAttributeMaxDynamicSharedMemorySize, (int)smem);

    dim3 grid(B_TOT / ROWS);      // 128 blocks
    dim3 block(NTHREADS);         // 832 threads (2 warp-aligned k-groups)
    lstm2_ksplit_kernel<<<grid, block, smem>>>(
        x, Wih1, Whh1, bih1, bhh1, Wih2, Whh2, bih2, bhh2, Wlin, blin, out);
}

// round 6
// speedup vs baseline: 1.2092x; 1.2092x over previous
#include <cuda_runtime.h>

// Fixed problem shapes
#define NS      51
#define NG      204
#define T_LEN   2048
#define B_TOT   8192
#define ROWS    64
#define HP      68                 // float pitch per k-row of h
#define HSZ     (NS * HP)
#define WQP     52                 // float4 pitch per k-row of weight quads
#define A_END   224                // group A: tid in [0,224), active < 204 (7 warps)
#define NTHREADS 640               // group B: tid in [224,640), active first 408

typedef unsigned long long ull;

__device__ __forceinline__ ull pack2(float lo, float hi) {
    ull r; asm("mov.b64 %0, {%1, %2};" : "=l"(r) : "f"(lo), "f"(hi)); return r;
}
__device__ __forceinline__ ull fma2(ull a, ull b, ull c) {
    ull d; asm("fma.rn.f32x2 %0, %1, %2, %3;" : "=l"(d) : "l"(a), "l"(b), "l"(c)); return d;
}
__device__ __forceinline__ float2 unpack2(ull v) {
    float lo, hi; asm("mov.b64 {%0, %1}, %2;" : "=f"(lo), "=f"(hi) : "l"(v));
    return make_float2(lo, hi);
}
__device__ __forceinline__ float sigm(float v) {
    return 1.0f / (1.0f + __expf(-v));
}
__device__ __forceinline__ float tanh_fast(float v) {
    return 2.0f / (1.0f + __expf(-2.0f * v)) - 1.0f;
}

__device__ __forceinline__ void lstm_act2(ull Ai, ull Af, ull Ag, ull Ao,
                                          float* c, float* hn) {
    float2 ai = unpack2(Ai), af = unpack2(Af), ag = unpack2(Ag), ao = unpack2(Ao);
    float cx = fmaf(sigm(af.x), c[0], sigm(ai.x) * tanh_fast(ag.x));
    c[0] = cx;  hn[0] = sigm(ao.x) * tanh_fast(cx);
    float cy = fmaf(sigm(af.y), c[1], sigm(ai.y) * tanh_fast(ag.y));
    c[1] = cy;  hn[1] = sigm(ao.y) * tanh_fast(cy);
}

// Layer-1 over 8 rows (4 packs) for unit j: reads h1r, writes h1w, updates cst[8].
__device__ __forceinline__ void layer1_pass(
    int j, int rowbase, const float* __restrict__ xcur,
    const float* __restrict__ h1r, float* __restrict__ h1w,
    const float4* __restrict__ wq1,
    const ull* wxd, const ull* b1d, float* cst)
{
    ull a0[4], a1[4], a2[4], a3[4];
    ulonglong2 xA = *(const ulonglong2*)(xcur + rowbase);
    ulonglong2 xB = *(const ulonglong2*)(xcur + rowbase + 4);
    ull xp[4] = {xA.x, xA.y, xB.x, xB.y};
    #pragma unroll
    for (int p = 0; p < 4; ++p) {
        a0[p] = fma2(xp[p], wxd[0], b1d[0]);
        a1[p] = fma2(xp[p], wxd[1], b1d[1]);
        a2[p] = fma2(xp[p], wxd[2], b1d[2]);
        a3[p] = fma2(xp[p], wxd[3], b1d[3]);
    }
    #pragma unroll 3
    for (int k = 0; k < NS; ++k) {
        float4 w = wq1[k * WQP + j];
        ull w0 = pack2(w.x, w.x), w1 = pack2(w.y, w.y);
        ull w2 = pack2(w.z, w.z), w3 = pack2(w.w, w.w);
        const float* hp = h1r + k * HP + rowbase;
        ulonglong2 hA = *(const ulonglong2*)hp;
        ulonglong2 hB = *(const ulonglong2*)(hp + 4);
        ull hv[4] = {hA.x, hA.y, hB.x, hB.y};
        #pragma unroll
        for (int p = 0; p < 4; ++p) {
            a0[p] = fma2(hv[p], w0, a0[p]);
            a1[p] = fma2(hv[p], w1, a1[p]);
            a2[p] = fma2(hv[p], w2, a2[p]);
            a3[p] = fma2(hv[p], w3, a3[p]);
        }
    }
    float hn[8];
    #pragma unroll
    for (int p = 0; p < 4; ++p)
        lstm_act2(a0[p], a1[p], a2[p], a3[p], cst + 2 * p, hn + 2 * p);
    float* dst = h1w + j * HP + rowbase;
    *(float4*)dst       = make_float4(hn[0], hn[1], hn[2], hn[3]);
    *(float4*)(dst + 4) = make_float4(hn[4], hn[5], hn[6], hn[7]);
}

__global__ __launch_bounds__(NTHREADS, 1)
void lstm2_pipe_kernel(
    const float* __restrict__ x,      // [B, T]
    const float* __restrict__ Wih1,   // [204, 1]
    const float* __restrict__ Whh1,   // [204, 51]
    const float* __restrict__ bih1,
    const float* __restrict__ bhh1,
    const float* __restrict__ Wih2,   // [204, 51]
    const float* __restrict__ Whh2,   // [204, 51]
    const float* __restrict__ bih2,
    const float* __restrict__ bhh2,
    const float* __restrict__ Wlin,   // [1, 51]
    const float* __restrict__ blin,
    float* __restrict__ out)          // [B, T]
{
    extern __shared__ float sm[];
    float4* wq1  = (float4*)sm;                       // [NS][WQP]
    float4* wqi2 = wq1  + NS * WQP;
    float4* wqh2 = wqi2 + NS * WQP;
    float*  h1b  = (float*)(wqh2 + NS * WQP);         // [2][NS][HP]
    float*  h2b  = h1b + 2 * HSZ;                     // [2][NS][HP]
    float*  b1s  = h2b + 2 * HSZ;                     // [NG]
    float*  b2s  = b1s + NG;
    float*  wi1s = b2s + NG;
    float*  wls  = wi1s + NG;                         // [52]
    float*  xs   = wls + 52;                          // [2][64]

    const int tid = threadIdx.x;
    const int rb  = blockIdx.x * ROWS;

    // ---- init ----
    for (int i = tid; i < NG * NS; i += NTHREADS) {
        int g = i / NS, k = i % NS;
        int jj = g % NS, gi = g / NS;
        ((float*)&wq1 [k * WQP + jj])[gi] = Whh1[i];
        ((float*)&wqi2[k * WQP + jj])[gi] = Wih2[i];
        ((float*)&wqh2[k * WQP + jj])[gi] = Whh2[i];
    }
    for (int i = tid; i < NG; i += NTHREADS) {
        b1s[i]  = bih1[i] + bhh1[i];
        b2s[i]  = bih2[i] + bhh2[i];
        wi1s[i] = Wih1[i];
    }
    for (int i = tid; i < NS; i += NTHREADS) wls[i] = Wlin[i];
    for (int i = tid; i < 2 * HSZ; i += NTHREADS) { h1b[i] = 0.0f; h2b[i] = 0.0f; }
    if (tid < ROWS) {                       // x(0) into slot 0
        xs[tid]      = x[(size_t)(rb + tid) * T_LEN];
        xs[64 + tid] = x[(size_t)(rb + tid) * T_LEN + 1];   // x(1) into slot 1
    }
    const float blin_v = blin[0];
    __syncthreads();

    const bool inA = (tid < A_END);
    // Group A mapping (active < 204): 4 slices x 16 rows
    const int rA  = tid;
    const int jA  = rA % NS;
    const int slA = (rA / NS) & 3;
    const int r0A = slA * 16;
    // Group B mapping (active < 408): 8 slices x 8 rows
    const int rB  = tid - A_END;
    const int jB  = (rB < 408) ? (rB % NS) : 0;
    const int slB = (rB < 408) ? (rB / NS) : 0;
    const int r0B = slB * 8;

    // packed constants
    ull wxd[4], b1d[4], b2d[4];
    {
        const int j = inA ? jA : jB;
        #pragma unroll
        for (int gi = 0; gi < 4; ++gi) {
            float wv  = wi1s[j + gi * NS];
            float bv1 = b1s[j + gi * NS];
            float bv2 = b2s[j + gi * NS];
            wxd[gi] = pack2(wv, wv);
            b1d[gi] = pack2(bv1, bv1);
            b2d[gi] = pack2(bv2, bv2);
        }
    }

    float cst[16];          // A: c1 for 16 rows ; B: c2 for 8 rows (uses [0..7])
    #pragma unroll
    for (int i = 0; i < 16; ++i) cst[i] = 0.0f;

    // ---- prologue: A computes h1(0) from x(0), h1_init=0 (reads buf1 zeros, writes buf0)
    if (inA && rA < 204) {
        layer1_pass(jA, r0A,     xs,      h1b + HSZ, h1b, wq1, wxd, b1d, cst);
        layer1_pass(jA, r0A + 8, xs,      h1b + HSZ, h1b, wq1, wxd, b1d, cst + 8);
    }
    __syncthreads();

    // ---- pipelined main loop: iteration it runs L1(it+1) [group A] || L2(it) [group B]
    for (int it = 0; it < T_LEN; ++it) {
        const int bf = it & 1;
        const float* h1cur = h1b + bf * HSZ;
        float*       h1nxt = h1b + (bf ^ 1) * HSZ;
        const float* h2cur = h2b + bf * HSZ;
        float*       h2nxt = h2b + (bf ^ 1) * HSZ;

        if (inA) {
            if (rA < 204 && it + 1 < T_LEN) {
                const float* xcur = xs + ((it + 1) & 1) * 64;
                layer1_pass(jA, r0A,     xcur, h1cur, h1nxt, wq1, wxd, b1d, cst);
                layer1_pass(jA, r0A + 8, xcur, h1cur, h1nxt, wq1, wxd, b1d, cst + 8);
            }
            if (rA < ROWS) {
                if (it > 0) {           // project h2(it-1), stable in h2cur
                    float acc = blin_v;
                    #pragma unroll 4
                    for (int k = 0; k < NS; ++k)
                        acc = fmaf(h2cur[k * HP + rA], wls[k], acc);
                    out[(size_t)(rb + rA) * T_LEN + (it - 1)] = acc;
                }
            } else if (rA < 2 * ROWS && rA < 204) {
                int rr = rA - ROWS;
                if (it + 2 < T_LEN)     // prefetch x(it+2) into slot it&1
                    xs[(it & 1) * 64 + rr] =
                        x[(size_t)(rb + rr) * T_LEN + (it + 2)];
            }
        } else if (rB < 408) {
            // ----- Group B: layer-2 for step it: h2(it) = L2(h1(it), h2(it-1)) -----
            ull a0[4], a1[4], a2[4], a3[4];
            #pragma unroll
            for (int p = 0; p < 4; ++p) {
                a0[p] = b2d[0]; a1[p] = b2d[1]; a2[p] = b2d[2]; a3[p] = b2d[3];
            }
            #pragma unroll 3
            for (int k = 0; k < NS; ++k) {
                float4 wi = wqi2[k * WQP + jB];
                float4 wh = wqh2[k * WQP + jB];
                ull wi0 = pack2(wi.x, wi.x), wi1d = pack2(wi.y, wi.y);
                ull wi2d = pack2(wi.z, wi.z), wi3 = pack2(wi.w, wi.w);
                ull wh0 = pack2(wh.x, wh.x), wh1d = pack2(wh.y, wh.y);
                ull wh2d = pack2(wh.z, wh.z), wh3 = pack2(wh.w, wh.w);
                const float* p1 = h1cur + k * HP + r0B;
                const float* p2 = h2cur + k * HP + r0B;
                ulonglong2 h1A = *(const ulonglong2*)p1;
                ulonglong2 h1B2 = *(const ulonglong2*)(p1 + 4);
                ulonglong2 h2A = *(const ulonglong2*)p2;
                ulonglong2 h2B2 = *(const ulonglong2*)(p2 + 4);
                ull hv1[4] = {h1A.x, h1A.y, h1B2.x, h1B2.y};
                ull hv2[4] = {h2A.x, h2A.y, h2B2.x, h2B2.y};
                #pragma unroll
                for (int p = 0; p < 4; ++p) {
                    a0[p] = fma2(hv1[p], wi0,  a0[p]);
                    a1[p] = fma2(hv1[p], wi1d, a1[p]);
                    a2[p] = fma2(hv1[p], wi2d, a2[p]);
                    a3[p] = fma2(hv1[p], wi3,  a3[p]);
                    a0[p] = fma2(hv2[p], wh0,  a0[p]);
                    a1[p] = fma2(hv2[p], wh1d, a1[p]);
                    a2[p] = fma2(hv2[p], wh2d, a2[p]);
                    a3[p] = fma2(hv2[p], wh3,  a3[p]);
                }
            }
            float hn[8];
            #pragma unroll
            for (int p = 0; p < 4; ++p)
                lstm_act2(a0[p], a1[p], a2[p], a3[p], cst + 2 * p, hn + 2 * p);
            float* dst = h2nxt + jB * HP + r0B;
            *(float4*)dst       = make_float4(hn[0], hn[1], hn[2], hn[3]);
            *(float4*)(dst + 4) = make_float4(hn[4], hn[5], hn[6], hn[7]);
        }
        __syncthreads();   // the single per-step barrier
    }

    // ---- final projection: h2(T-1) lives in h2b[T_LEN & 1] = buffer 0 ----
    if (inA && rA < ROWS) {
        const float* h2f = h2b + (T_LEN & 1) * HSZ;
        float acc = blin_v;
        #pragma unroll 4
        for (int k = 0; k < NS; ++k)
            acc = fmaf(h2f[k * HP + rA], wls[k], acc);
        out[(size_t)(rb + rA) * T_LEN + (T_LEN - 1)] = acc;
    }
}

extern "C" void kernel_launch(void* const* d_in, const int* in_sizes, int n_in,
                              void* d_out, int out_size) {
    const float* x    = (const float*)d_in[0];
    const float* Wih1 = (const float*)d_in[1];
    const float* Whh1 = (const float*)d_in[2];
    const float* bih1 = (const float*)d_in[3];
    const float* bhh1 = (const float*)d_in[4];
    const float* Wih2 = (const float*)d_in[5];
    const float* Whh2 = (const float*)d_in[6];
    const float* bih2 = (const float*)d_in[7];
    const float* bhh2 = (const float*)d_in[8];
    const float* Wlin = (const float*)d_in[9];
    const float* blin = (const float*)d_in[10];
    float* out = (float*)d_out;

    size_t smem = (size_t)(3 * NS * WQP * 4 + 4 * HSZ + 3 * NG + 52 + 128)
                  * sizeof(float);
    cudaFuncSetAttribute(lstm2_pipe_kernel,
                         cudaFuncAttributeMaxDynamicSharedMemorySize, (int)smem);

    dim3 grid(B_TOT / ROWS);      // 128 blocks
    dim3 block(NTHREADS);         // 640 threads: 7 warps L1 + 13 warps L2
    lstm2_pipe_kernel<<<grid, block, smem>>>(
        x, Wih1, Whh1, bih1, bhh1, Wih2, Whh2, bih2, bhh2, Wlin, blin, out);
}

// round 9
// speedup vs baseline: 1.5137x; 1.2518x over previous
#include <cuda_runtime.h>
#include <cuda_bf16.h>
#include <cstdint>

// ---------------- fixed shapes ----------------
#define NS      51
#define T_LEN   2048
#define B_TOT   8192
#define M_ROWS  64
#define NCTA    (B_TOT / M_ROWS)      // 128
#define NTHREADS 384                  // 12 warps = 2 m-groups x 6 n-groups

// SMEM tiles
#define APITCH  528                   // A: [64 rows][256 bf16]  (h1hi|h1lo|h2hi|h2lo)
#define B1P     272                   // B1: [208 n][128 bf16]   (W1hi|W1lo)
#define B2P     528                   // B2: [208 n][256 bf16]   (Wi2hi|Wi2lo|Wh2hi|Wh2lo)

#define OFF_A   0
#define A_BYTES (64 * APITCH)                 // 33792
#define OFF_B1  (OFF_A + A_BYTES)
#define B1_BYTES (208 * B1P)                  // 56576
#define OFF_B2  (OFF_B1 + B1_BYTES)
#define B2_BYTES (208 * B2P)                  // 109824
#define OFF_B1Q (OFF_B2 + B2_BYTES)           // float4[52]
#define OFF_B2Q (OFF_B1Q + 832)
#define OFF_WXQ (OFF_B2Q + 832)
#define OFF_WLS (OFF_WXQ + 832)               // float[52] (+pad)
#define OFF_YW  (OFF_WLS + 224)               // float[64][8]
#define SMEM_TOTAL (OFF_YW + 64 * 8 * 4)      // 204960

typedef uint32_t u32;

// ---------------- helpers ----------------
__device__ __forceinline__ u32 smem_u32(const void* p) {
    u32 a;
    asm("{ .reg .u64 t; cvta.to.shared.u64 t, %1; cvt.u32.u64 %0, t; }" : "=r"(a) : "l"(p));
    return a;
}
__device__ __forceinline__ void ldsm4(u32* r, u32 addr) {
    asm volatile("ldmatrix.sync.aligned.m8n8.x4.shared.b16 {%0,%1,%2,%3}, [%4];"
                 : "=r"(r[0]), "=r"(r[1]), "=r"(r[2]), "=r"(r[3]) : "r"(addr));
}
__device__ __forceinline__ void mma_bf16(float* c, const u32* a, const u32* b) {
    asm volatile("mma.sync.aligned.m16n8k16.row.col.f32.bf16.bf16.f32 "
                 "{%0,%1,%2,%3}, {%4,%5,%6,%7}, {%8,%9}, {%0,%1,%2,%3};"
                 : "+f"(c[0]), "+f"(c[1]), "+f"(c[2]), "+f"(c[3])
                 : "r"(a[0]), "r"(a[1]), "r"(a[2]), "r"(a[3]), "r"(b[0]), "r"(b[1]));
}
__device__ __forceinline__ float sigm(float v) { return 1.0f / (1.0f + __expf(-v)); }
__device__ __forceinline__ float tanh_fast(float v) { return 2.0f / (1.0f + __expf(-2.0f * v)) - 1.0f; }

// A-fragment (m16k16) address: m0 = absolute first row of this 16-row tile.  [R9 FIX: caller passes 32*mg+16*mt]
__device__ __forceinline__ u32 a_addr(u32 sbA, int m0, int kchunk, int lane) {
    int r  = m0 + (lane & 15);
    int cb = kchunk * 32 + ((lane >> 4) << 4);
    return sbA + r * APITCH + cb;
}
// B-fragment x4 (one n8 tile, two k16 tiles starting at kchunk)
__device__ __forceinline__ u32 b_addr(u32 sbB, int pitch, int nt, int kchunk, int lane) {
    int n  = nt * 8 + (lane & 7);
    int cb = kchunk * 32 + ((lane >> 3) << 4);
    return sbB + n * pitch + cb;
}

// Regroup D-frag gates: after this each lane owns (i,f,g,o) of ONE (row,unit).
// even lane (t even): row r = lane>>2 ; odd lane: row r+8.
__device__ __forceinline__ void regroup(const float* C, int lane,
                                        float& gi_, float& gf, float& gg, float& go) {
    float v  = (lane & 1) ? C[0] : C[2];
    float sv = __shfl_xor_sync(0xFFFFFFFFu, v, 1);
    float w  = (lane & 1) ? C[1] : C[3];
    float sw = __shfl_xor_sync(0xFFFFFFFFu, w, 1);
    if (lane & 1) { gi_ = sv;   gf = sw;   gg = C[2]; go = C[3]; }
    else          { gi_ = C[0]; gf = C[1]; gg = sv;   go = sw;  }
}

__device__ __forceinline__ void store_h(char* smem, int row, int colbase, float h) {
    __nv_bfloat16 hh = __float2bfloat16(h);
    __nv_bfloat16 hl = __float2bfloat16(h - __bfloat162float(hh));
    *(__nv_bfloat16*)(smem + OFF_A + row * APITCH + colbase * 2)        = hh;
    *(__nv_bfloat16*)(smem + OFF_A + row * APITCH + (colbase + 64) * 2) = hl;
}

// Layer-1 epilogue
__device__ __forceinline__ void epi_l1(
    float acc[2][5][4], int cnt, int nt0, int lane, int jpar, const int* rows,
    const float4* b1q, const float4* wxq, const float* xv,
    float c1[2][5], char* smem)
{
    #pragma unroll
    for (int mt = 0; mt < 2; ++mt) {
        #pragma unroll
        for (int nti = 0; nti < 5; ++nti) if (nti < cnt) {
            float gi_, gf, gg, go;
            regroup(acc[mt][nti], lane, gi_, gf, gg, go);
            int j = 2 * (nt0 + nti) + jpar;
            float4 b  = b1q[j];
            float4 wx = wxq[j];
            float pi = fmaf(xv[mt], wx.x, gi_ + b.x);
            float pf = fmaf(xv[mt], wx.y, gf + b.y);
            float pg = fmaf(xv[mt], wx.z, gg + b.z);
            float po = fmaf(xv[mt], wx.w, go + b.w);
            float cn = fmaf(sigm(pf), c1[mt][nti], sigm(pi) * tanh_fast(pg));
            c1[mt][nti] = cn;
            float h = sigm(po) * tanh_fast(cn);
            if (j < NS) store_h(smem, rows[mt], j, h);
        }
    }
}

// Layer-2 epilogue (+ y partials)
__device__ __forceinline__ void epi_l2(
    float acc[2][5][4], int cnt, int nt0, int lane, int jpar, const int* rows,
    const float4* b2q, const float* wls,
    float c2[2][5], char* smem, float* yw, int ng)
{
    #pragma unroll
    for (int mt = 0; mt < 2; ++mt) {
        float yp = 0.0f;
        #pragma unroll
        for (int nti = 0; nti < 5; ++nti) if (nti < cnt) {
            float gi_, gf, gg, go;
            regroup(acc[mt][nti], lane, gi_, gf, gg, go);
            int j = 2 * (nt0 + nti) + jpar;
            float4 b = b2q[j];
            float pi = gi_ + b.x, pf = gf + b.y, pg = gg + b.z, po = go + b.w;
            float cn = fmaf(sigm(pf), c2[mt][nti], sigm(pi) * tanh_fast(pg));
            c2[mt][nti] = cn;
            float h = sigm(po) * tanh_fast(cn);
            if (j < NS) {
                store_h(smem, rows[mt], 128 + j, h);
                yp = fmaf(wls[j], h, yp);
            }
        }
        float ys = yp + __shfl_xor_sync(0xFFFFFFFFu, yp, 2);
        if (!(lane & 2)) yw[rows[mt] * 8 + ng] = ys;
    }
}

__global__ __launch_bounds__(NTHREADS, 1)
void lstm2_hmma_kernel(
    const float* __restrict__ x,      // [B, T]
    const float* __restrict__ Wih1,   // [204, 1]
    const float* __restrict__ Whh1,   // [204, 51]
    const float* __restrict__ bih1,
    const float* __restrict__ bhh1,
    const float* __restrict__ Wih2,   // [204, 51]
    const float* __restrict__ Whh2,   // [204, 51]
    const float* __restrict__ bih2,
    const float* __restrict__ bhh2,
    const float* __restrict__ Wlin,   // [1, 51]
    const float* __restrict__ blin,
    float* __restrict__ out)          // [B, T]
{
    extern __shared__ char smem[];
    const u32 sb = smem_u32(smem);
    const int tid  = threadIdx.x;
    const int wid  = tid >> 5;
    const int lane = tid & 31;
    const int mg   = wid / 6;                 // m-group 0/1 (rows 0-31 / 32-63)
    const int ng   = wid % 6;                 // n-group
    const int cnt  = (ng < 2) ? 5 : 4;
    const int nt0  = (ng < 2) ? 5 * ng : 10 + 4 * (ng - 2);
    const int rb   = blockIdx.x * M_ROWS;

    for (int i = tid; i < SMEM_TOTAL / 4; i += NTHREADS) ((u32*)smem)[i] = 0;
    __syncthreads();

    float4* b1q = (float4*)(smem + OFF_B1Q);
    float4* b2q = (float4*)(smem + OFF_B2Q);
    float4* wxq = (float4*)(smem + OFF_WXQ);
    float*  wls = (float*)(smem + OFF_WLS);
    float*  yw  = (float*)(smem + OFF_YW);

    // ---- weights: B row n = 4*j + gi, hi/lo bf16 split ----
    for (int idx = tid; idx < 208 * NS; idx += NTHREADS) {
        int n = idx / NS, m = idx % NS;
        int j = n >> 2, gi = n & 3;
        if (j < NS) {
            int g = gi * NS + j;
            float w1  = Whh1[g * NS + m];
            float wi2 = Wih2[g * NS + m];
            float wh2 = Whh2[g * NS + m];
            __nv_bfloat16 h, l;
            h = __float2bfloat16(w1);  l = __float2bfloat16(w1 - __bfloat162float(h));
            *(__nv_bfloat16*)(smem + OFF_B1 + n * B1P + m * 2)        = h;
            *(__nv_bfloat16*)(smem + OFF_B1 + n * B1P + (64 + m) * 2) = l;
            h = __float2bfloat16(wi2); l = __float2bfloat16(wi2 - __bfloat162float(h));
            *(__nv_bfloat16*)(smem + OFF_B2 + n * B2P + m * 2)        = h;
            *(__nv_bfloat16*)(smem + OFF_B2 + n * B2P + (64 + m) * 2) = l;
            h = __float2bfloat16(wh2); l = __float2bfloat16(wh2 - __bfloat162float(h));
            *(__nv_bfloat16*)(smem + OFF_B2 + n * B2P + (128 + m) * 2) = h;
            *(__nv_bfloat16*)(smem + OFF_B2 + n * B2P + (192 + m) * 2) = l;
        }
    }
    for (int j = tid; j < NS; j += NTHREADS) {
        b1q[j] = make_float4(bih1[j] + bhh1[j], bih1[j + NS] + bhh1[j + NS],
                             bih1[j + 2 * NS] + bhh1[j + 2 * NS], bih1[j + 3 * NS] + bhh1[j + 3 * NS]);
        b2q[j] = make_float4(bih2[j] + bhh2[j], bih2[j + NS] + bhh2[j + NS],
                             bih2[j + 2 * NS] + bhh2[j + 2 * NS], bih2[j + 3 * NS] + bhh2[j + 3 * NS]);
        wxq[j] = make_float4(Wih1[j], Wih1[j + NS], Wih1[j + 2 * NS], Wih1[j + 3 * NS]);
        wls[j] = Wlin[j];
    }
    __syncthreads();

    const float blin_v = blin[0];
    const int rbase = 32 * mg + (lane >> 2) + 8 * (lane & 1);
    const int rows[2] = {rbase, rbase + 16};
    const int jpar = (lane >> 1) & 1;
    const u32 sbA = sb + OFF_A;
    const u32 sbB1 = sb + OFF_B1;
    const u32 sbB2 = sb + OFF_B2;
    const int m0base = 32 * mg;               // [R9 FIX] absolute A-row base for this warp

    float c1[2][5], c2[2][5];
    #pragma unroll
    for (int mt = 0; mt < 2; ++mt)
        #pragma unroll
        for (int i = 0; i < 5; ++i) { c1[mt][i] = 0.0f; c2[mt][i] = 0.0f; }

    // ---- prologue: h1(0) = L1(x(0), h=0, c=0) ----
    {
        float acc0[2][5][4];
        #pragma unroll
        for (int mt = 0; mt < 2; ++mt)
            #pragma unroll
            for (int i = 0; i < 5; ++i)
                #pragma unroll
                for (int q = 0; q < 4; ++q) acc0[mt][i][q] = 0.0f;
        float xv0[2];
        #pragma unroll
        for (int mt = 0; mt < 2; ++mt)
            xv0[mt] = __ldg(&x[(size_t)(rb + rows[mt]) * T_LEN]);
        epi_l1(acc0, cnt, nt0, lane, jpar, rows, b1q, wxq, xv0, c1, smem);
    }
    __syncthreads();

    // ---- main loop: step t uses tile {h1(t), h2(t-1)} ----
    for (int t = 0; t < T_LEN; ++t) {
        float xv[2];
        #pragma unroll
        for (int mt = 0; mt < 2; ++mt)
            xv[mt] = (t + 1 < T_LEN)
                   ? __ldg(&x[(size_t)(rb + rows[mt]) * T_LEN + t + 1]) : 0.0f;

        float acc1[2][5][4], acc2[2][5][4];
        #pragma unroll
        for (int mt = 0; mt < 2; ++mt)
            #pragma unroll
            for (int i = 0; i < 5; ++i)
                #pragma unroll
                for (int q = 0; q < 4; ++q) { acc1[mt][i][q] = 0.0f; acc2[mt][i][q] = 0.0f; }

        // ---- P1: acc1 += h1 * W1  (hi*hi + lo*hi + hi*lo) ----
        #pragma unroll
        for (int half = 0; half < 2; ++half) {
            u32 ahi[2][2][4], alo[2][2][4];
            #pragma unroll
            for (int mt = 0; mt < 2; ++mt)
                #pragma unroll
                for (int kk = 0; kk < 2; ++kk) {
                    ldsm4(ahi[mt][kk], a_addr(sbA, m0base + 16 * mt, 2 * half + kk, lane));
                    ldsm4(alo[mt][kk], a_addr(sbA, m0base + 16 * mt, 4 + 2 * half + kk, lane));
                }
            #pragma unroll
            for (int nti = 0; nti < 5; ++nti) if (nti < cnt) {
                int nt = nt0 + nti;
                u32 bh[4], bl[4];
                ldsm4(bh, b_addr(sbB1, B1P, nt, 2 * half, lane));
                ldsm4(bl, b_addr(sbB1, B1P, nt, 4 + 2 * half, lane));
                #pragma unroll
                for (int mt = 0; mt < 2; ++mt)
                    #pragma unroll
                    for (int kk = 0; kk < 2; ++kk) {
                        mma_bf16(acc1[mt][nti], ahi[mt][kk], bh + 2 * kk);
                        mma_bf16(acc1[mt][nti], alo[mt][kk], bh + 2 * kk);
                        mma_bf16(acc1[mt][nti], ahi[mt][kk], bl + 2 * kk);
                    }
            }
        }

        // ---- P2: acc2 += h1 * Wi2 ----
        #pragma unroll
        for (int half = 0; half < 2; ++half) {
            u32 ahi[2][2][4], alo[2][2][4];
            #pragma unroll
            for (int mt = 0; mt < 2; ++mt)
                #pragma unroll
                for (int kk = 0; kk < 2; ++kk) {
                    ldsm4(ahi[mt][kk], a_addr(sbA, m0base + 16 * mt, 2 * half + kk, lane));
                    ldsm4(alo[mt][kk], a_addr(sbA, m0base + 16 * mt, 4 + 2 * half + kk, lane));
                }
            #pragma unroll
            for (int nti = 0; nti < 5; ++nti) if (nti < cnt) {
                int nt = nt0 + nti;
                u32 bh[4], bl[4];
                ldsm4(bh, b_addr(sbB2, B2P, nt, 2 * half, lane));
                ldsm4(bl, b_addr(sbB2, B2P, nt, 4 + 2 * half, lane));
                #pragma unroll
                for (int mt = 0; mt < 2; ++mt)
                    #pragma unroll
                    for (int kk = 0; kk < 2; ++kk) {
                        mma_bf16(acc2[mt][nti], ahi[mt][kk], bh + 2 * kk);
                        mma_bf16(acc2[mt][nti], alo[mt][kk], bh + 2 * kk);
                        mma_bf16(acc2[mt][nti], ahi[mt][kk], bl + 2 * kk);
                    }
            }
        }

        // ---- P3: acc2 += h2 * Wh2 ----
        #pragma unroll
        for (int half = 0; half < 2; ++half) {
            u32 ahi[2][2][4], alo[2][2][4];
            #pragma unroll
            for (int mt = 0; mt < 2; ++mt)
                #pragma unroll
                for (int kk = 0; kk < 2; ++kk) {
                    ldsm4(ahi[mt][kk], a_addr(sbA, m0base + 16 * mt, 8 + 2 * half + kk, lane));
                    ldsm4(alo[mt][kk], a_addr(sbA, m0base + 16 * mt, 12 + 2 * half + kk, lane));
                }
            #pragma unroll
            for (int nti = 0; nti < 5; ++nti) if (nti < cnt) {
                int nt = nt0 + nti;
                u32 bh[4], bl[4];
                ldsm4(bh, b_addr(sbB2, B2P, nt, 8 + 2 * half, lane));
                ldsm4(bl, b_addr(sbB2, B2P, nt, 12 + 2 * half, lane));
                #pragma unroll
                for (int mt = 0; mt < 2; ++mt)
                    #pragma unroll
                    for (int kk = 0; kk < 2; ++kk) {
                        mma_bf16(acc2[mt][nti], ahi[mt][kk], bh + 2 * kk);
                        mma_bf16(acc2[mt][nti], alo[mt][kk], bh + 2 * kk);
                        mma_bf16(acc2[mt][nti], ahi[mt][kk], bl + 2 * kk);
                    }
            }
        }

        __syncthreads();   // all ldmatrix reads of the A tile complete

        epi_l2(acc2, cnt, nt0, lane, jpar, rows, b2q, wls, c2, smem, yw, ng);
        epi_l1(acc1, cnt, nt0, lane, jpar, rows, b1q, wxq, xv, c1, smem);

        __syncthreads();   // h stores + y partials visible

        if (tid < M_ROWS) {
            float acc = blin_v;
            #pragma unroll
            for (int g2 = 0; g2 < 6; ++g2) acc += yw[tid * 8 + g2];
            out[(size_t)(rb + tid) * T_LEN + t] = acc;
        }
    }
}

extern "C" void kernel_launch(void* const* d_in, const int* in_sizes, int n_in,
                              void* d_out, int out_size) {
    const float* x    = (const float*)d_in[0];
    const float* Wih1 = (const float*)d_in[1];
    const float* Whh1 = (const float*)d_in[2];
    const float* bih1 = (const float*)d_in[3];
    const float* bhh1 = (const float*)d_in[4];
    const float* Wih2 = (const float*)d_in[5];
    const float* Whh2 = (const float*)d_in[6];
    const float* bih2 = (const float*)d_in[7];
    const float* bhh2 = (const float*)d_in[8];
    const float* Wlin = (const float*)d_in[9];
    const float* blin = (const float*)d_in[10];
    float* out = (float*)d_out;

    cudaFuncSetAttribute(lstm2_hmma_kernel,
                         cudaFuncAttributeMaxDynamicSharedMemorySize, SMEM_TOTAL);

    dim3 grid(NCTA);          // 128 CTAs x 64 rows
    dim3 block(NTHREADS);     // 384 threads
    lstm2_hmma_kernel<<<grid, block, SMEM_TOTAL>>>(
        x, Wih1, Whh1, bih1, bhh1, Wih2, Whh2, bih2, bhh2, Wlin, blin, out);
}